// round 12
// baseline (speedup 1.0000x reference)
#include <cuda_runtime.h>
#include <cuda_bf16.h>
#include <math.h>
#include <stdint.h>

// Problem constants
#define TOK_L   4096
#define NBATCH  2
#define NTOK    8192
#define CDIM    256
#define DI      512
#define NSTATE  16
#define RRANK   32
#define CHUNK   64
#define NCHUNK  64
#define NFUSED  640          // 512 (dt) + 32 (B,C) + 96 pad

// ------------------------- scratch (device globals) -------------------------
__device__ float g_res   [NTOK * CDIM];
__device__ float g_decrow[NTOK * CDIM];
__device__ float g_rdt   [NTOK * DI];
__device__ float g_hend  [NBATCH * NCHUNK * DI * NSTATE];
__device__ float g_Pend  [NBATCH * NCHUNK * DI * NSTATE];
__device__ float g_hstart[NBATCH * NCHUNK * DI * NSTATE];

// bf16 activations
__device__ __nv_bfloat16 g_decbf  [NTOK * CDIM];
__device__ __nv_bfloat16 g_encbf  [NTOK * CDIM];
__device__ __nv_bfloat16 g_encp   [NTOK * DI];
__device__ __nv_bfloat16 g_gate   [NTOK * DI];
__device__ __nv_bfloat16 g_combbf [NTOK * DI];
__device__ __nv_bfloat16 g_xm     [NTOK * DI];
__device__ __nv_bfloat16 g_z      [NTOK * DI];
__device__ __nv_bfloat16 g_u      [NTOK * DI];
__device__ __nv_bfloat16 g_dt     [NTOK * DI];
__device__ __nv_bfloat16 g_dtu    [NTOK * DI];
__device__ __nv_bfloat16 g_bc     [NTOK * 32];
__device__ __nv_bfloat16 g_ybf    [NTOK * DI];
__device__ __nv_bfloat16 g_gatedbf[NTOK * DI];
// bf16 weights, row-major [K][N]
__device__ __nv_bfloat16 g_wdec  [CDIM * 2 * DI];
__device__ __nv_bfloat16 g_wenc  [CDIM * DI];
__device__ __nv_bfloat16 g_win   [DI * 2 * DI];
__device__ __nv_bfloat16 g_wmout [DI * DI];
__device__ __nv_bfloat16 g_wout  [DI * CDIM];
__device__ __nv_bfloat16 g_wfused[DI * NFUSED];

// ------------------------- helpers -----------------------------------------
__device__ __forceinline__ float sigmoidf_(float x) { return 1.f / (1.f + __expf(-x)); }

#define CP_ASYNC16(dst, src) \
    asm volatile("cp.async.cg.shared.global [%0], [%1], 16;\n" :: "r"(dst), "l"(src))
#define CP_COMMIT() asm volatile("cp.async.commit_group;\n" ::: "memory")
#define CP_WAIT1()  asm volatile("cp.async.wait_group 1;\n" ::: "memory")
#define CP_WAIT0()  asm volatile("cp.async.wait_group 0;\n" ::: "memory")

#define LDSM_X4(r0,r1,r2,r3,addr) \
    asm volatile("ldmatrix.sync.aligned.m8n8.x4.shared.b16 {%0,%1,%2,%3}, [%4];" \
        : "=r"(r0),"=r"(r1),"=r"(r2),"=r"(r3) : "r"(addr))
#define LDSM_X4T(r0,r1,r2,r3,addr) \
    asm volatile("ldmatrix.sync.aligned.m8n8.x4.trans.shared.b16 {%0,%1,%2,%3}, [%4];" \
        : "=r"(r0),"=r"(r1),"=r"(r2),"=r"(r3) : "r"(addr))

#define MMA16816(d, a, b) \
    asm volatile("mma.sync.aligned.m16n8k16.row.col.f32.bf16.bf16.f32 " \
        "{%0,%1,%2,%3}, {%4,%5,%6,%7}, {%8,%9}, {%0,%1,%2,%3};" \
        : "+f"(d[0]),"+f"(d[1]),"+f"(d[2]),"+f"(d[3]) \
        : "r"(a[0]),"r"(a[1]),"r"(a[2]),"r"(a[3]), "r"(b[0]),"r"(b[1]))

// ------------------------- epilogue functors -------------------------------
struct EpiEnc {
    const float* b;
    __device__ void operator()(int t, int j, float a) const {
        g_encp[(size_t)t * DI + j] = __float2bfloat16(a + b[j]);
    }
};
struct EpiDec {
    const float* b;
    __device__ void operator()(int t, int j, float a) const {
        float v = a + b[j];
        if (j < DI) {
            float e = __bfloat162float(g_encp[(size_t)t * DI + j]);
            g_combbf[(size_t)t * DI + j] = __float2bfloat16(v * sigmoidf_(e) + e);
        } else {
            g_gate[(size_t)t * DI + (j - DI)] = __float2bfloat16(v);
        }
    }
};
struct EpiXZ {
    const float* b;
    __device__ void operator()(int t, int j, float a) const {
        float v = a + b[j];
        if (j < DI) g_xm[(size_t)t * DI + j] = __float2bfloat16(v);
        else        g_z [(size_t)t * DI + (j - DI)] = __float2bfloat16(v);
    }
};
struct EpiFused {
    const float* dtb;
    __device__ void operator()(int t, int j, float a) const {
        if (j < DI) {
            float x = a + dtb[j];
            float ex = __expf(x);
            float sp, r;
            if (x > 20.f) { sp = x; r = __expf(-x); }
            else          { sp = log1pf(ex); r = 1.f / (1.f + ex); }
            float uv = __bfloat162float(g_u[(size_t)t * DI + j]);
            g_dt [(size_t)t * DI + j] = __float2bfloat16(sp);
            g_dtu[(size_t)t * DI + j] = __float2bfloat16(sp * uv);
            g_rdt[(size_t)t * DI + j] = r;
        } else if (j < DI + 32) {
            g_bc[(size_t)t * 32 + (j - DI)] = __float2bfloat16(a);
        }
    }
};
struct EpiMout {
    const float* b;
    __device__ void operator()(int t, int j, float a) const {
        float v = a + b[j];
        float g = __bfloat162float(g_gate[(size_t)t * DI + j]);
        g_gatedbf[(size_t)t * DI + j] = __float2bfloat16(v * sigmoidf_(g));
    }
};
struct EpiOut {
    const float* b;
    __device__ void operator()(int t, int j, float a) const {
        g_res[(size_t)t * CDIM + j] = a + b[j] + g_decrow[(size_t)t * CDIM + j];
    }
};

// ------------------- bf16 tensor-core GEMM (round-8 mainloop) --------------
// New: smem-staged coalesced epilogue.
template <class Epi>
__global__ __launch_bounds__(256, 3) void gemm_bf(
    const __nv_bfloat16* __restrict__ A, const __nv_bfloat16* __restrict__ W,
    int K, int N, int lda, Epi epi)
{
    extern __shared__ char smem[];
    const int ASZ = 64 * 128;        // 64 rows x 64 bf16 (128B rows)
    const int BSZ = 64 * 256;        // 64 k-rows x 128 bf16 (256B rows)
    uint32_t sbase = (uint32_t)__cvta_generic_to_shared(smem);

    int tid = threadIdx.x;
    int w = tid >> 5, lane = tid & 31;
    int wm = w >> 2, wn = w & 3;     // 2 x 4 warps; warp tile 32x32
    int t0 = blockIdx.y * 64, n0 = blockIdx.x * 128;

    const __nv_bfloat16* Ab = A + (size_t)t0 * lda;
    const __nv_bfloat16* Wb = W + n0;

    auto loadStage = [&](int s, int k0) {
        uint32_t as = sbase + s * (ASZ + BSZ);
        uint32_t bs = as + ASZ;
#pragma unroll
        for (int r = 0; r < 2; r++) {
            int idx = tid + 256 * r;
            int m = idx >> 3, kb = idx & 7;
            uint32_t off = m * 128 + ((kb ^ (m & 7)) << 4);
            CP_ASYNC16(as + off, Ab + (size_t)m * lda + k0 + kb * 8);
        }
#pragma unroll
        for (int r = 0; r < 4; r++) {
            int idx = tid + 256 * r;
            int k = idx >> 4, nb = idx & 15;
            uint32_t off = k * 256 + ((nb >> 3) << 7) + (((nb & 7) ^ (k & 7)) << 4);
            CP_ASYNC16(bs + off, Wb + (size_t)(k0 + k) * N + nb * 8);
        }
    };

    float acc[2][4][4];
#pragma unroll
    for (int i = 0; i < 2; i++)
#pragma unroll
        for (int j = 0; j < 4; j++)
#pragma unroll
            for (int c = 0; c < 4; c++) acc[i][j][c] = 0.f;

    int nk = K / 64;
    loadStage(0, 0);
    CP_COMMIT();
    if (nk > 1) loadStage(1, 64);
    CP_COMMIT();

    for (int kt = 0; kt < nk; kt++) {
        CP_WAIT1();
        __syncthreads();
        int s = kt % 3;
        if (kt + 2 < nk) loadStage((kt + 2) % 3, (kt + 2) * 64);
        CP_COMMIT();

        uint32_t as = sbase + s * (ASZ + BSZ);
        uint32_t bs = as + ASZ;
        int sub = lane >> 3;
#pragma unroll
        for (int ks = 0; ks < 4; ks++) {
            uint32_t afr[2][4];
            uint32_t bfr[4][2];
#pragma unroll
            for (int i = 0; i < 2; i++) {
                int row = wm * 32 + i * 16 + (lane & 7) + ((sub & 1) << 3);
                int kb = ks * 2 + (sub >> 1);
                uint32_t addr = as + row * 128 + ((kb ^ (row & 7)) << 4);
                LDSM_X4(afr[i][0], afr[i][1], afr[i][2], afr[i][3], addr);
            }
#pragma unroll
            for (int p = 0; p < 2; p++) {
                int k = ks * 16 + (lane & 7) + ((sub & 1) << 3);
                int nb = wn * 4 + p * 2 + (sub >> 1);
                uint32_t addr = bs + k * 256 + ((nb >> 3) << 7) + (((nb & 7) ^ (k & 7)) << 4);
                uint32_t r0, r1, r2, r3;
                LDSM_X4T(r0, r1, r2, r3, addr);
                bfr[p * 2][0] = r0;     bfr[p * 2][1] = r1;
                bfr[p * 2 + 1][0] = r2; bfr[p * 2 + 1][1] = r3;
            }
#pragma unroll
            for (int i = 0; i < 2; i++)
#pragma unroll
                for (int j = 0; j < 4; j++) MMA16816(acc[i][j], afr[i], bfr[j]);
        }
    }

    // ---- staged coalesced epilogue ----
    CP_WAIT0();
    __syncthreads();                  // mainloop smem dead; reuse as fp32 tile
    float* fsm = reinterpret_cast<float*>(smem);
    const int LDC = 132;
    int r0 = wm * 32 + (lane >> 2);
    int c0 = wn * 32 + (lane & 3) * 2;
#pragma unroll
    for (int i = 0; i < 2; i++)
#pragma unroll
        for (int j = 0; j < 4; j++) {
            int rr = r0 + i * 16, cc = c0 + j * 8;
            fsm[rr * LDC + cc]           = acc[i][j][0];
            fsm[rr * LDC + cc + 1]       = acc[i][j][1];
            fsm[(rr + 8) * LDC + cc]     = acc[i][j][2];
            fsm[(rr + 8) * LDC + cc + 1] = acc[i][j][3];
        }
    __syncthreads();
#pragma unroll 4
    for (int rr = 0; rr < 32; rr++) {
        int row = rr * 2 + (tid >> 7);    // 0..63
        int col = tid & 127;              // coalesced across warp
        epi(t0 + row, n0 + col, fsm[row * LDC + col]);
    }
}

// ------------------------- weight prep kernels ------------------------------
__global__ __launch_bounds__(256) void wcomb_k(
    const float* __restrict__ xproj, const float* __restrict__ dtw)
{
    int idx = blockIdx.x * 256 + threadIdx.x;
    if (idx >= DI * NFUSED) return;
    int k = idx / NFUSED, j = idx % NFUSED;
    float v = 0.f;
    if (j < DI) {
#pragma unroll
        for (int r = 0; r < RRANK; r++)
            v = fmaf(xproj[k * 64 + r], dtw[r * DI + j], v);
    } else if (j < DI + 32) {
        v = xproj[k * 64 + 32 + (j - DI)];
    }
    g_wfused[idx] = __float2bfloat16(v);
}

#define SZ_WDEC (CDIM * 2 * DI)
#define SZ_WENC (CDIM * DI)
#define SZ_WIN  (DI * 2 * DI)
#define SZ_WMOUT (DI * DI)
#define SZ_WOUT (DI * CDIM)
#define SZ_ALL  (SZ_WDEC + SZ_WENC + SZ_WIN + SZ_WMOUT + SZ_WOUT)

__global__ __launch_bounds__(256) void f2bf_all(
    const float* __restrict__ dec_w, const float* __restrict__ enc_w,
    const float* __restrict__ in_w, const float* __restrict__ m_out_w,
    const float* __restrict__ out_w)
{
    int i = blockIdx.x * 256 + threadIdx.x;
    if (i < SZ_WDEC) { g_wdec[i] = __float2bfloat16(dec_w[i]); return; }
    i -= SZ_WDEC;
    if (i < SZ_WENC) { g_wenc[i] = __float2bfloat16(enc_w[i]); return; }
    i -= SZ_WENC;
    if (i < SZ_WIN)  { g_win[i] = __float2bfloat16(in_w[i]); return; }
    i -= SZ_WIN;
    if (i < SZ_WMOUT){ g_wmout[i] = __float2bfloat16(m_out_w[i]); return; }
    i -= SZ_WMOUT;
    if (i < SZ_WOUT) { g_wout[i] = __float2bfloat16(out_w[i]); }
}

// ------------------------- NCHW -> row-major (bf16; dec also fp32) ---------
__global__ __launch_bounds__(256) void nchw_to_bf2(
    const float* __restrict__ dec, const float* __restrict__ enc)
{
    __shared__ float sm[32][257];
    int tid = threadIdx.x;
    int nblk = gridDim.x >> 1;
    int which = blockIdx.x >= nblk;
    const float* in = which ? enc : dec;
    __nv_bfloat16* out = which ? g_encbf : g_decbf;
    int t0 = (blockIdx.x - which * nblk) * 32;
    int bt = t0 >> 12, l0 = t0 & (TOK_L - 1);
    const float* src = in + (size_t)bt * CDIM * TOK_L + l0;
#pragma unroll 4
    for (int r = 0; r < 32; r++) {
        int idx = tid + 256 * r;
        int c = idx >> 5, l = idx & 31;
        sm[l][c] = src[(size_t)c * TOK_L + l];
    }
    __syncthreads();
#pragma unroll 4
    for (int r = 0; r < 32; r++) {
        int idx = tid + 256 * r;
        int c = idx & 255, l = idx >> 8;
        float v = sm[l][c];
        out[(size_t)(t0 + l) * CDIM + c] = __float2bfloat16(v);
        if (!which) g_decrow[(size_t)(t0 + l) * CDIM + c] = v;
    }
}

// ------------------------- depthwise causal conv (K=4) + SiLU --------------
__global__ __launch_bounds__(256) void conv_silu_k(
    const float* __restrict__ w, const float* __restrict__ bias)
{
    int t = blockIdx.x;
    int d = blockIdx.y * 256 + threadIdx.x;
    int l = t & (TOK_L - 1);
    float acc = bias[d];
#pragma unroll
    for (int k = 0; k < 4; k++) {
        int li = l - 3 + k;
        if (li >= 0)
            acc = fmaf(__bfloat162float(g_xm[(size_t)(t - 3 + k) * DI + d]), w[d * 4 + k], acc);
    }
    g_u[(size_t)t * DI + d] = __float2bfloat16(acc * sigmoidf_(acc));
}

// ------------------------- chunked selective scan (16 states / thread) ------
__device__ __forceinline__ void pow_ladder(float r, float* w) {
    w[0] = r;
    w[1] = r * r;
    w[2] = w[1] * r;    w[3] = w[1] * w[1];
    w[4] = w[3] * r;    w[5] = w[3] * w[1];  w[6] = w[3] * w[2];  w[7] = w[3] * w[3];
    w[8] = w[7] * r;    w[9] = w[7] * w[1];  w[10] = w[7] * w[2]; w[11] = w[7] * w[3];
    w[12] = w[7] * w[4];w[13] = w[7] * w[5]; w[14] = w[7] * w[6]; w[15] = w[7] * w[7];
}

// defined-behavior BC load: 16x bf16x2 loads (uniform per block -> L1 broadcast)
__device__ __forceinline__ void load_bc16(size_t tt, float* Bv, float* Cv) {
    const __nv_bfloat162* p = reinterpret_cast<const __nv_bfloat162*>(&g_bc[tt * 32]);
#pragma unroll
    for (int i = 0; i < 8; i++) {
        float2 f = __bfloat1622float2(p[i]);
        Bv[i * 2] = f.x; Bv[i * 2 + 1] = f.y;
    }
#pragma unroll
    for (int i = 0; i < 8; i++) {
        float2 g = __bfloat1622float2(p[8 + i]);
        Cv[i * 2] = g.x; Cv[i * 2 + 1] = g.y;
    }
}

__global__ __launch_bounds__(256) void scan_pass1(const float* __restrict__ A_log)
{
    int gid = blockIdx.x * 256 + threadIdx.x;
    int d = gid & (DI - 1);
    int c = (gid >> 9) & (NCHUNK - 1);
    int b = gid >> 15;

    float a[NSTATE];
    bool fast = true;
#pragma unroll
    for (int n = 0; n < NSTATE; n++) {
        a[n] = -__expf(A_log[d * NSTATE + n]);
        fast = fast && (fabsf(a[n] + (float)(n + 1)) < 1e-5f * (n + 1));
    }

    float h[NSTATE];
#pragma unroll
    for (int n = 0; n < NSTATE; n++) h[n] = 0.f;

    size_t base = (size_t)b * TOK_L + (size_t)c * CHUNK;
    size_t oidx = (((size_t)b * NCHUNK + c) * DI + d) * NSTATE;
    float P[NSTATE];

    if (fast) {
        float p = 1.f;
        for (int l = 0; l < CHUNK; l++) {
            size_t tt = base + l;
            float dtu = __bfloat162float(g_dtu[tt * DI + d]);
            float r   = g_rdt[tt * DI + d];
            p *= r;
            float w[NSTATE], Bv[NSTATE], Cv[NSTATE];
            pow_ladder(r, w);
            load_bc16(tt, Bv, Cv);
#pragma unroll
            for (int n = 0; n < NSTATE; n++)
                h[n] = fmaf(h[n], w[n], dtu * Bv[n]);
        }
        pow_ladder(p, P);
    } else {
        float dtsum = 0.f;
        for (int l = 0; l < CHUNK; l++) {
            size_t tt = base + l;
            float dtv = __bfloat162float(g_dt [tt * DI + d]);
            float dtu = __bfloat162float(g_dtu[tt * DI + d]);
            dtsum += dtv;
            float Bv[NSTATE], Cv[NSTATE];
            load_bc16(tt, Bv, Cv);
#pragma unroll
            for (int n = 0; n < NSTATE; n++)
                h[n] = fmaf(h[n], __expf(dtv * a[n]), dtu * Bv[n]);
        }
#pragma unroll
        for (int n = 0; n < NSTATE; n++) P[n] = __expf(a[n] * dtsum);
    }

    float4* ho = reinterpret_cast<float4*>(&g_hend[oidx]);
    float4* po = reinterpret_cast<float4*>(&g_Pend[oidx]);
#pragma unroll
    for (int q = 0; q < 4; q++) {
        ho[q] = make_float4(h[q * 4], h[q * 4 + 1], h[q * 4 + 2], h[q * 4 + 3]);
        po[q] = make_float4(P[q * 4], P[q * 4 + 1], P[q * 4 + 2], P[q * 4 + 3]);
    }
}

__global__ __launch_bounds__(256) void scan_pass2()
{
    int tid = blockIdx.x * 256 + threadIdx.x;
    int b  = tid >> 13;
    int dn = tid & 8191;
    float h = 0.f;
    for (int c = 0; c < NCHUNK; c++) {
        size_t idx = ((size_t)(b * NCHUNK + c)) * 8192 + dn;
        g_hstart[idx] = h;
        h = g_hend[idx] + g_Pend[idx] * h;
    }
}

__global__ __launch_bounds__(256) void scan_pass3(
    const float* __restrict__ A_log, const float* __restrict__ Dp)
{
    int gid = blockIdx.x * 256 + threadIdx.x;
    int d = gid & (DI - 1);
    int c = (gid >> 9) & (NCHUNK - 1);
    int b = gid >> 15;

    float a[NSTATE];
    bool fast = true;
#pragma unroll
    for (int n = 0; n < NSTATE; n++) {
        a[n] = -__expf(A_log[d * NSTATE + n]);
        fast = fast && (fabsf(a[n] + (float)(n + 1)) < 1e-5f * (n + 1));
    }
    float Dv = Dp[d];

    size_t sidx = (((size_t)b * NCHUNK + c) * DI + d) * NSTATE;
    float h[NSTATE];
    {
        const float4* hi = reinterpret_cast<const float4*>(&g_hstart[sidx]);
#pragma unroll
        for (int q = 0; q < 4; q++) {
            float4 v = hi[q];
            h[q * 4] = v.x; h[q * 4 + 1] = v.y; h[q * 4 + 2] = v.z; h[q * 4 + 3] = v.w;
        }
    }

    size_t base = (size_t)b * TOK_L + (size_t)c * CHUNK;
    for (int l = 0; l < CHUNK; l++) {
        size_t tt = base + l;
        float dtu = __bfloat162float(g_dtu[tt * DI + d]);
        float uv  = __bfloat162float(g_u  [tt * DI + d]);
        float zv  = __bfloat162float(g_z  [tt * DI + d]);
        float w[NSTATE], Bv[NSTATE], Cv[NSTATE];
        if (fast) {
            float r = g_rdt[tt * DI + d];
            pow_ladder(r, w);
        } else {
            float dtv = __bfloat162float(g_dt[tt * DI + d]);
#pragma unroll
            for (int n = 0; n < NSTATE; n++) w[n] = __expf(dtv * a[n]);
        }
        load_bc16(tt, Bv, Cv);
        float y0 = 0.f, y1 = 0.f, y2 = 0.f, y3 = 0.f;
#pragma unroll
        for (int n = 0; n < NSTATE; n += 4) {
            h[n]     = fmaf(h[n],     w[n],     dtu * Bv[n]);
            h[n + 1] = fmaf(h[n + 1], w[n + 1], dtu * Bv[n + 1]);
            h[n + 2] = fmaf(h[n + 2], w[n + 2], dtu * Bv[n + 2]);
            h[n + 3] = fmaf(h[n + 3], w[n + 3], dtu * Bv[n + 3]);
            y0 = fmaf(h[n],     Cv[n],     y0);
            y1 = fmaf(h[n + 1], Cv[n + 1], y1);
            y2 = fmaf(h[n + 2], Cv[n + 2], y2);
            y3 = fmaf(h[n + 3], Cv[n + 3], y3);
        }
        float y = (y0 + y1) + (y2 + y3);
        y = (y + uv * Dv) * (zv * sigmoidf_(zv));
        g_ybf[tt * DI + d] = __float2bfloat16(y);
    }
}

// ------------------------- LayerNorm + NCHW output -------------------------
__global__ __launch_bounds__(256) void ln_k(
    const float* __restrict__ g, const float* __restrict__ be,
    float* __restrict__ out)
{
    __shared__ float sm[32][257];
    int tid = threadIdx.x;
    int warp = tid >> 5, lane = tid & 31;
    int t0 = blockIdx.x * 32;

    for (int i = 0; i < 4; i++) {
        int tl = warp * 4 + i;
        int t  = t0 + tl;
        const float* row = g_res + (size_t)t * CDIM;
        float v[8];
        float s = 0.f, sq = 0.f;
#pragma unroll
        for (int r = 0; r < 2; r++) {
            float4 p = reinterpret_cast<const float4*>(row)[lane * 2 + r];
            v[r * 4] = p.x; v[r * 4 + 1] = p.y; v[r * 4 + 2] = p.z; v[r * 4 + 3] = p.w;
        }
#pragma unroll
        for (int k = 0; k < 8; k++) { s += v[k]; sq += v[k] * v[k]; }
#pragma unroll
        for (int o = 16; o; o >>= 1) {
            s  += __shfl_xor_sync(0xffffffffu, s,  o);
            sq += __shfl_xor_sync(0xffffffffu, sq, o);
        }
        float mu  = s * (1.f / CDIM);
        float var = sq * (1.f / CDIM) - mu * mu;
        float inv = rsqrtf(var + 1e-5f);
#pragma unroll
        for (int k = 0; k < 8; k++) {
            int c = lane * 8 + k;
            sm[tl][c] = (v[k] - mu) * inv * g[c] + be[c];
        }
    }
    __syncthreads();

    int bt = t0 >> 12;
    int l0 = t0 & (TOK_L - 1);
#pragma unroll 4
    for (int r = 0; r < 32; r++) {
        int idx = tid + 256 * r;
        int l = idx & 31;
        int c = idx >> 5;
        out[((size_t)bt * CDIM + c) * TOK_L + l0 + l] = sm[l][c];
    }
}

// ------------------------- launch ------------------------------------------
extern "C" void kernel_launch(void* const* d_in, const int* in_sizes, int n_in,
                              void* d_out, int out_size)
{
    const float* decoder  = (const float*)d_in[0];
    const float* encoder  = (const float*)d_in[1];
    const float* dec_w    = (const float*)d_in[2];
    const float* dec_b    = (const float*)d_in[3];
    const float* enc_w    = (const float*)d_in[4];
    const float* enc_b    = (const float*)d_in[5];
    const float* out_w    = (const float*)d_in[6];
    const float* out_b    = (const float*)d_in[7];
    const float* ln_g     = (const float*)d_in[8];
    const float* ln_b     = (const float*)d_in[9];
    const float* in_w     = (const float*)d_in[10];
    const float* in_b     = (const float*)d_in[11];
    const float* conv_w   = (const float*)d_in[12];
    const float* conv_b   = (const float*)d_in[13];
    const float* x_proj_w = (const float*)d_in[14];
    const float* dt_w     = (const float*)d_in[15];
    const float* dt_b     = (const float*)d_in[16];
    const float* A_log    = (const float*)d_in[17];
    const float* D_param  = (const float*)d_in[18];
    const float* m_out_w  = (const float*)d_in[19];
    const float* m_out_b  = (const float*)d_in[20];
    float* out = (float*)d_out;

    const int SMEM_GEMM = 3 * (64 * 128 + 64 * 256);   // 73728 >= 64*132*4
    static int attr_done = 0;
    if (!attr_done) {
        cudaFuncSetAttribute(gemm_bf<EpiEnc  >, cudaFuncAttributeMaxDynamicSharedMemorySize, SMEM_GEMM);
        cudaFuncSetAttribute(gemm_bf<EpiDec  >, cudaFuncAttributeMaxDynamicSharedMemorySize, SMEM_GEMM);
        cudaFuncSetAttribute(gemm_bf<EpiXZ   >, cudaFuncAttributeMaxDynamicSharedMemorySize, SMEM_GEMM);
        cudaFuncSetAttribute(gemm_bf<EpiFused>, cudaFuncAttributeMaxDynamicSharedMemorySize, SMEM_GEMM);
        cudaFuncSetAttribute(gemm_bf<EpiMout >, cudaFuncAttributeMaxDynamicSharedMemorySize, SMEM_GEMM);
        cudaFuncSetAttribute(gemm_bf<EpiOut  >, cudaFuncAttributeMaxDynamicSharedMemorySize, SMEM_GEMM);
        attr_done = 1;
    }

    dim3 blk(256);
    const int MB = NTOK / 64;   // 128 M-tiles

    __nv_bfloat16 *wdec, *wenc, *win, *wmout, *wout, *wfused;
    __nv_bfloat16 *decbf, *encbf, *combbf, *ubf, *ybf, *gatedbf;
    cudaGetSymbolAddress((void**)&wdec,   g_wdec);
    cudaGetSymbolAddress((void**)&wenc,   g_wenc);
    cudaGetSymbolAddress((void**)&win,    g_win);
    cudaGetSymbolAddress((void**)&wmout,  g_wmout);
    cudaGetSymbolAddress((void**)&wout,   g_wout);
    cudaGetSymbolAddress((void**)&wfused, g_wfused);
    cudaGetSymbolAddress((void**)&decbf,  g_decbf);
    cudaGetSymbolAddress((void**)&encbf,  g_encbf);
    cudaGetSymbolAddress((void**)&combbf, g_combbf);
    cudaGetSymbolAddress((void**)&ubf,    g_u);
    cudaGetSymbolAddress((void**)&ybf,    g_ybf);
    cudaGetSymbolAddress((void**)&gatedbf,g_gatedbf);

    // weight prep + input transpose
    f2bf_all<<<(SZ_ALL + 255) / 256, blk>>>(dec_w, enc_w, in_w, m_out_w, out_w);
    wcomb_k<<<(DI * NFUSED + 255) / 256, blk>>>(x_proj_w, dt_w);
    nchw_to_bf2<<<2 * (NTOK / 32), blk>>>(decoder, encoder);

    // 1. enc_p = enc @ enc_w + enc_b               (K=256, N=512)
    gemm_bf<EpiEnc  ><<<dim3(DI / 128, MB), blk, SMEM_GEMM>>>(encbf, wenc, CDIM, DI, CDIM, EpiEnc{enc_b});
    // 2. dec_proj -> combined(bf16) + gate          (K=256, N=1024)
    gemm_bf<EpiDec  ><<<dim3(2 * DI / 128, MB), blk, SMEM_GEMM>>>(decbf, wdec, CDIM, 2 * DI, CDIM, EpiDec{dec_b});
    // 3. xz = combined @ in_w -> xm, z              (K=512, N=1024)
    gemm_bf<EpiXZ   ><<<dim3(2 * DI / 128, MB), blk, SMEM_GEMM>>>(combbf, win, DI, 2 * DI, DI, EpiXZ{in_b});
    // 4. depthwise conv + SiLU -> u (bf16)
    conv_silu_k<<<dim3(NTOK, DI / 256), blk>>>(conv_w, conv_b);
    // 5. fused: dt/r/dtu + B/C                      (K=512, N=640)
    gemm_bf<EpiFused><<<dim3(NFUSED / 128, MB), blk, SMEM_GEMM>>>(ubf, wfused, DI, NFUSED, DI, EpiFused{dt_b});
    // 6-8. chunked selective scan (16 states/thread)
    scan_pass1<<<NBATCH * NCHUNK * DI / 256, blk>>>(A_log);
    scan_pass2<<<NBATCH * DI * NSTATE / 256, blk>>>();
    scan_pass3<<<NBATCH * NCHUNK * DI / 256, blk>>>(A_log, D_param);
    // 9. processed = y @ m_out_w + b, * sigmoid(gate)  (K=512, N=512)
    gemm_bf<EpiMout ><<<dim3(DI / 128, MB), blk, SMEM_GEMM>>>(ybf, wmout, DI, DI, DI, EpiMout{m_out_b});
    // 10. out = gated @ out_w + out_b + dec        (K=512, N=256)
    gemm_bf<EpiOut  ><<<dim3(CDIM / 128, MB), blk, SMEM_GEMM>>>(gatedbf, wout, DI, CDIM, DI, EpiOut{out_b});
    // 11. LayerNorm + transpose to NCHW
    ln_k<<<NTOK / 32, blk>>>(ln_g, ln_b, out);
}

// round 13
// speedup vs baseline: 1.2622x; 1.2622x over previous
#include <cuda_runtime.h>
#include <cuda_bf16.h>
#include <math.h>
#include <stdint.h>

// Problem constants
#define TOK_L   4096
#define NBATCH  2
#define NTOK    8192
#define CDIM    256
#define DI      512
#define NSTATE  16
#define RRANK   32
#define CHUNK   64
#define NCHUNK  64
#define NFUSED  640          // 512 (dt) + 32 (B,C) + 96 pad

// ------------------------- scratch (device globals) -------------------------
__device__ float g_res   [NTOK * CDIM];
__device__ float g_decrow[NTOK * CDIM];
__device__ float g_rdt   [NTOK * DI];
__device__ float g_hend  [NBATCH * NCHUNK * DI * NSTATE];
__device__ float g_Pend  [NBATCH * NCHUNK * DI * NSTATE];
__device__ float g_hstart[NBATCH * NCHUNK * DI * NSTATE];

// bf16 activations
__device__ __nv_bfloat16 g_decbf  [NTOK * CDIM];
__device__ __nv_bfloat16 g_encbf  [NTOK * CDIM];
__device__ __nv_bfloat16 g_encp   [NTOK * DI];
__device__ __nv_bfloat16 g_gate   [NTOK * DI];
__device__ __nv_bfloat16 g_combbf [NTOK * DI];
__device__ __nv_bfloat16 g_xm     [NTOK * DI];
__device__ __nv_bfloat16 g_z      [NTOK * DI];
__device__ __nv_bfloat16 g_u      [NTOK * DI];
__device__ __nv_bfloat16 g_dt     [NTOK * DI];
__device__ __nv_bfloat16 g_dtu    [NTOK * DI];
__device__ __nv_bfloat16 g_bc     [NTOK * 32];
__device__ __nv_bfloat16 g_ybf    [NTOK * DI];
__device__ __nv_bfloat16 g_gatedbf[NTOK * DI];
// bf16 weights, row-major [K][N]
__device__ __nv_bfloat16 g_wdec  [CDIM * 2 * DI];
__device__ __nv_bfloat16 g_wenc  [CDIM * DI];
__device__ __nv_bfloat16 g_win   [DI * 2 * DI];
__device__ __nv_bfloat16 g_wmout [DI * DI];
__device__ __nv_bfloat16 g_wout  [DI * CDIM];
__device__ __nv_bfloat16 g_wfused[DI * NFUSED];

// ------------------------- helpers -----------------------------------------
__device__ __forceinline__ float sigmoidf_(float x) { return 1.f / (1.f + __expf(-x)); }

#define CP_ASYNC16(dst, src) \
    asm volatile("cp.async.cg.shared.global [%0], [%1], 16;\n" :: "r"(dst), "l"(src))
#define CP_COMMIT() asm volatile("cp.async.commit_group;\n" ::: "memory")
#define CP_WAIT1()  asm volatile("cp.async.wait_group 1;\n" ::: "memory")

#define LDSM_X4(r0,r1,r2,r3,addr) \
    asm volatile("ldmatrix.sync.aligned.m8n8.x4.shared.b16 {%0,%1,%2,%3}, [%4];" \
        : "=r"(r0),"=r"(r1),"=r"(r2),"=r"(r3) : "r"(addr))
#define LDSM_X4T(r0,r1,r2,r3,addr) \
    asm volatile("ldmatrix.sync.aligned.m8n8.x4.trans.shared.b16 {%0,%1,%2,%3}, [%4];" \
        : "=r"(r0),"=r"(r1),"=r"(r2),"=r"(r3) : "r"(addr))

#define MMA16816(d, a, b) \
    asm volatile("mma.sync.aligned.m16n8k16.row.col.f32.bf16.bf16.f32 " \
        "{%0,%1,%2,%3}, {%4,%5,%6,%7}, {%8,%9}, {%0,%1,%2,%3};" \
        : "+f"(d[0]),"+f"(d[1]),"+f"(d[2]),"+f"(d[3]) \
        : "r"(a[0]),"r"(a[1]),"r"(a[2]),"r"(a[3]), "r"(b[0]),"r"(b[1]))

// ------------------------- epilogue functors -------------------------------
struct EpiEnc {
    const float* b;
    __device__ void operator()(int t, int j, float a) const {
        g_encp[(size_t)t * DI + j] = __float2bfloat16(a + b[j]);
    }
};
struct EpiDec {
    const float* b;
    __device__ void operator()(int t, int j, float a) const {
        float v = a + b[j];
        if (j < DI) {
            float e = __bfloat162float(g_encp[(size_t)t * DI + j]);
            g_combbf[(size_t)t * DI + j] = __float2bfloat16(v * sigmoidf_(e) + e);
        } else {
            g_gate[(size_t)t * DI + (j - DI)] = __float2bfloat16(v);
        }
    }
};
struct EpiXZ {
    const float* b;
    __device__ void operator()(int t, int j, float a) const {
        float v = a + b[j];
        if (j < DI) g_xm[(size_t)t * DI + j] = __float2bfloat16(v);
        else        g_z [(size_t)t * DI + (j - DI)] = __float2bfloat16(v);
    }
};
struct EpiFused {
    const float* dtb;
    __device__ void operator()(int t, int j, float a) const {
        if (j < DI) {
            float x = a + dtb[j];
            float ex = __expf(x);
            float sp, r;
            if (x > 20.f) { sp = x; r = 1.f / ex; }
            else          { sp = log1pf(ex); r = 1.f / (1.f + ex); }
            float uv = __bfloat162float(g_u[(size_t)t * DI + j]);
            g_dt [(size_t)t * DI + j] = __float2bfloat16(sp);
            g_dtu[(size_t)t * DI + j] = __float2bfloat16(sp * uv);
            g_rdt[(size_t)t * DI + j] = r;
        } else if (j < DI + 32) {
            g_bc[(size_t)t * 32 + (j - DI)] = __float2bfloat16(a);
        }
    }
};
struct EpiMout {
    const float* b;
    __device__ void operator()(int t, int j, float a) const {
        float v = a + b[j];
        float g = __bfloat162float(g_gate[(size_t)t * DI + j]);
        g_gatedbf[(size_t)t * DI + j] = __float2bfloat16(v * sigmoidf_(g));
    }
};
struct EpiOut {
    const float* b;
    __device__ void operator()(int t, int j, float a) const {
        g_res[(size_t)t * CDIM + j] = a + b[j] + g_decrow[(size_t)t * CDIM + j];
    }
};

// ------------------- bf16 tensor-core GEMM (round-8 proven) ----------------
template <class Epi>
__global__ __launch_bounds__(256, 3) void gemm_bf(
    const __nv_bfloat16* __restrict__ A, const __nv_bfloat16* __restrict__ W,
    int K, int N, int lda, Epi epi)
{
    extern __shared__ char smem[];
    const int ASZ = 64 * 128;        // 64 rows x 64 bf16 (128B rows)
    const int BSZ = 64 * 256;        // 64 k-rows x 128 bf16 (256B rows)
    uint32_t sbase = (uint32_t)__cvta_generic_to_shared(smem);

    int tid = threadIdx.x;
    int w = tid >> 5, lane = tid & 31;
    int wm = w >> 2, wn = w & 3;     // 2 x 4 warps; warp tile 32x32
    int t0 = blockIdx.y * 64, n0 = blockIdx.x * 128;

    const __nv_bfloat16* Ab = A + (size_t)t0 * lda;
    const __nv_bfloat16* Wb = W + n0;

    auto loadStage = [&](int s, int k0) {
        uint32_t as = sbase + s * (ASZ + BSZ);
        uint32_t bs = as + ASZ;
#pragma unroll
        for (int r = 0; r < 2; r++) {
            int idx = tid + 256 * r;
            int m = idx >> 3, kb = idx & 7;
            uint32_t off = m * 128 + ((kb ^ (m & 7)) << 4);
            CP_ASYNC16(as + off, Ab + (size_t)m * lda + k0 + kb * 8);
        }
#pragma unroll
        for (int r = 0; r < 4; r++) {
            int idx = tid + 256 * r;
            int k = idx >> 4, nb = idx & 15;
            uint32_t off = k * 256 + ((nb >> 3) << 7) + (((nb & 7) ^ (k & 7)) << 4);
            CP_ASYNC16(bs + off, Wb + (size_t)(k0 + k) * N + nb * 8);
        }
    };

    float acc[2][4][4];
#pragma unroll
    for (int i = 0; i < 2; i++)
#pragma unroll
        for (int j = 0; j < 4; j++)
#pragma unroll
            for (int c = 0; c < 4; c++) acc[i][j][c] = 0.f;

    int nk = K / 64;
    loadStage(0, 0);
    CP_COMMIT();
    if (nk > 1) loadStage(1, 64);
    CP_COMMIT();

    for (int kt = 0; kt < nk; kt++) {
        CP_WAIT1();
        __syncthreads();
        int s = kt % 3;
        if (kt + 2 < nk) loadStage((kt + 2) % 3, (kt + 2) * 64);
        CP_COMMIT();

        uint32_t as = sbase + s * (ASZ + BSZ);
        uint32_t bs = as + ASZ;
        int sub = lane >> 3;
#pragma unroll
        for (int ks = 0; ks < 4; ks++) {
            uint32_t afr[2][4];
            uint32_t bfr[4][2];
#pragma unroll
            for (int i = 0; i < 2; i++) {
                int row = wm * 32 + i * 16 + (lane & 7) + ((sub & 1) << 3);
                int kb = ks * 2 + (sub >> 1);
                uint32_t addr = as + row * 128 + ((kb ^ (row & 7)) << 4);
                LDSM_X4(afr[i][0], afr[i][1], afr[i][2], afr[i][3], addr);
            }
#pragma unroll
            for (int p = 0; p < 2; p++) {
                int k = ks * 16 + (lane & 7) + ((sub & 1) << 3);
                int nb = wn * 4 + p * 2 + (sub >> 1);
                uint32_t addr = bs + k * 256 + ((nb >> 3) << 7) + (((nb & 7) ^ (k & 7)) << 4);
                uint32_t r0, r1, r2, r3;
                LDSM_X4T(r0, r1, r2, r3, addr);
                bfr[p * 2][0] = r0;     bfr[p * 2][1] = r1;
                bfr[p * 2 + 1][0] = r2; bfr[p * 2 + 1][1] = r3;
            }
#pragma unroll
            for (int i = 0; i < 2; i++)
#pragma unroll
                for (int j = 0; j < 4; j++) MMA16816(acc[i][j], afr[i], bfr[j]);
        }
    }

    int rbase = t0 + wm * 32 + (lane >> 2);
    int cbase = n0 + wn * 32 + (lane & 3) * 2;
#pragma unroll
    for (int i = 0; i < 2; i++)
#pragma unroll
        for (int j = 0; j < 4; j++) {
            epi(rbase + i * 16,     cbase + j * 8,     acc[i][j][0]);
            epi(rbase + i * 16,     cbase + j * 8 + 1, acc[i][j][1]);
            epi(rbase + i * 16 + 8, cbase + j * 8,     acc[i][j][2]);
            epi(rbase + i * 16 + 8, cbase + j * 8 + 1, acc[i][j][3]);
        }
}

// ------------------------- weight prep kernels ------------------------------
__global__ __launch_bounds__(256) void wcomb_k(
    const float* __restrict__ xproj, const float* __restrict__ dtw)
{
    int idx = blockIdx.x * 256 + threadIdx.x;
    if (idx >= DI * NFUSED) return;
    int k = idx / NFUSED, j = idx % NFUSED;
    float v = 0.f;
    if (j < DI) {
#pragma unroll
        for (int r = 0; r < RRANK; r++)
            v = fmaf(xproj[k * 64 + r], dtw[r * DI + j], v);
    } else if (j < DI + 32) {
        v = xproj[k * 64 + 32 + (j - DI)];
    }
    g_wfused[idx] = __float2bfloat16(v);
}

#define SZ_WDEC (CDIM * 2 * DI)
#define SZ_WENC (CDIM * DI)
#define SZ_WIN  (DI * 2 * DI)
#define SZ_WMOUT (DI * DI)
#define SZ_WOUT (DI * CDIM)
#define SZ_ALL  (SZ_WDEC + SZ_WENC + SZ_WIN + SZ_WMOUT + SZ_WOUT)

__global__ __launch_bounds__(256) void f2bf_all(
    const float* __restrict__ dec_w, const float* __restrict__ enc_w,
    const float* __restrict__ in_w, const float* __restrict__ m_out_w,
    const float* __restrict__ out_w)
{
    int i = blockIdx.x * 256 + threadIdx.x;
    if (i < SZ_WDEC) { g_wdec[i] = __float2bfloat16(dec_w[i]); return; }
    i -= SZ_WDEC;
    if (i < SZ_WENC) { g_wenc[i] = __float2bfloat16(enc_w[i]); return; }
    i -= SZ_WENC;
    if (i < SZ_WIN)  { g_win[i] = __float2bfloat16(in_w[i]); return; }
    i -= SZ_WIN;
    if (i < SZ_WMOUT){ g_wmout[i] = __float2bfloat16(m_out_w[i]); return; }
    i -= SZ_WMOUT;
    if (i < SZ_WOUT) { g_wout[i] = __float2bfloat16(out_w[i]); }
}

// ------------------------- NCHW -> row-major (bf16; dec also fp32) ---------
__global__ __launch_bounds__(256) void nchw_to_bf2(
    const float* __restrict__ dec, const float* __restrict__ enc)
{
    __shared__ float sm[32][257];
    int tid = threadIdx.x;
    int nblk = gridDim.x >> 1;
    int which = blockIdx.x >= nblk;
    const float* in = which ? enc : dec;
    __nv_bfloat16* out = which ? g_encbf : g_decbf;
    int t0 = (blockIdx.x - which * nblk) * 32;
    int bt = t0 >> 12, l0 = t0 & (TOK_L - 1);
    const float* src = in + (size_t)bt * CDIM * TOK_L + l0;
#pragma unroll 4
    for (int r = 0; r < 32; r++) {
        int idx = tid + 256 * r;
        int c = idx >> 5, l = idx & 31;
        sm[l][c] = src[(size_t)c * TOK_L + l];
    }
    __syncthreads();
#pragma unroll 4
    for (int r = 0; r < 32; r++) {
        int idx = tid + 256 * r;
        int c = idx & 255, l = idx >> 8;
        float v = sm[l][c];
        out[(size_t)(t0 + l) * CDIM + c] = __float2bfloat16(v);
        if (!which) g_decrow[(size_t)(t0 + l) * CDIM + c] = v;
    }
}

// ------------------ depthwise causal conv (K=4) + SiLU, vectorized ---------
__global__ __launch_bounds__(256) void conv_silu_k(
    const float* __restrict__ w, const float* __restrict__ bias)
{
    int idx = blockIdx.x * 256 + threadIdx.x;   // NTOK * 64 threads
    int t = idx >> 6;
    int d0 = (idx & 63) << 3;
    int l = t & (TOK_L - 1);

    float wv[8][4];
#pragma unroll
    for (int i = 0; i < 8; i++) {
        float4 q = *reinterpret_cast<const float4*>(&w[(d0 + i) * 4]);
        wv[i][0] = q.x; wv[i][1] = q.y; wv[i][2] = q.z; wv[i][3] = q.w;
    }

    float acc[8];
#pragma unroll
    for (int i = 0; i < 8; i++) acc[i] = bias[d0 + i];

#pragma unroll
    for (int k = 0; k < 4; k++) {
        int li = l - 3 + k;
        if (li >= 0) {
            uint4 q = *reinterpret_cast<const uint4*>(&g_xm[(size_t)(t - 3 + k) * DI + d0]);
            float2 f0 = __bfloat1622float2(*reinterpret_cast<const __nv_bfloat162*>(&q.x));
            float2 f1 = __bfloat1622float2(*reinterpret_cast<const __nv_bfloat162*>(&q.y));
            float2 f2 = __bfloat1622float2(*reinterpret_cast<const __nv_bfloat162*>(&q.z));
            float2 f3 = __bfloat1622float2(*reinterpret_cast<const __nv_bfloat162*>(&q.w));
            acc[0] = fmaf(f0.x, wv[0][k], acc[0]);
            acc[1] = fmaf(f0.y, wv[1][k], acc[1]);
            acc[2] = fmaf(f1.x, wv[2][k], acc[2]);
            acc[3] = fmaf(f1.y, wv[3][k], acc[3]);
            acc[4] = fmaf(f2.x, wv[4][k], acc[4]);
            acc[5] = fmaf(f2.y, wv[5][k], acc[5]);
            acc[6] = fmaf(f3.x, wv[6][k], acc[6]);
            acc[7] = fmaf(f3.y, wv[7][k], acc[7]);
        }
    }

    uint4 o;
#pragma unroll
    for (int i = 0; i < 4; i++) {
        float a0 = acc[i * 2];     a0 = a0 * sigmoidf_(a0);
        float a1 = acc[i * 2 + 1]; a1 = a1 * sigmoidf_(a1);
        __nv_bfloat162 b2 = __floats2bfloat162_rn(a0, a1);
        uint32_t wrd = *reinterpret_cast<uint32_t*>(&b2);
        if (i == 0) o.x = wrd; else if (i == 1) o.y = wrd;
        else if (i == 2) o.z = wrd; else o.w = wrd;
    }
    *reinterpret_cast<uint4*>(&g_u[(size_t)t * DI + d0]) = o;
}

// ------------------------- chunked selective scan (16 states / thread) ------
__device__ __forceinline__ void pow_ladder(float r, float* w) {
    w[0] = r;
    w[1] = r * r;
    w[2] = w[1] * r;    w[3] = w[1] * w[1];
    w[4] = w[3] * r;    w[5] = w[3] * w[1];  w[6] = w[3] * w[2];  w[7] = w[3] * w[3];
    w[8] = w[7] * r;    w[9] = w[7] * w[1];  w[10] = w[7] * w[2]; w[11] = w[7] * w[3];
    w[12] = w[7] * w[4];w[13] = w[7] * w[5]; w[14] = w[7] * w[6]; w[15] = w[7] * w[7];
}

__device__ __forceinline__ void unpack2(uint32_t wrd, float* dst) {
    __nv_bfloat162 v;
    *reinterpret_cast<uint32_t*>(&v) = wrd;
    float2 f = __bfloat1622float2(v);
    dst[0] = f.x; dst[1] = f.y;
}

// 4x LDG.128, defined-behavior word extraction
__device__ __forceinline__ void load_bc16(size_t tt, float* Bv, float* Cv) {
    const uint4* p = reinterpret_cast<const uint4*>(&g_bc[tt * 32]);
    uint4 q0 = p[0], q1 = p[1], q2 = p[2], q3 = p[3];
    unpack2(q0.x, Bv);      unpack2(q0.y, Bv + 2);
    unpack2(q0.z, Bv + 4);  unpack2(q0.w, Bv + 6);
    unpack2(q1.x, Bv + 8);  unpack2(q1.y, Bv + 10);
    unpack2(q1.z, Bv + 12); unpack2(q1.w, Bv + 14);
    unpack2(q2.x, Cv);      unpack2(q2.y, Cv + 2);
    unpack2(q2.z, Cv + 4);  unpack2(q2.w, Cv + 6);
    unpack2(q3.x, Cv + 8);  unpack2(q3.y, Cv + 10);
    unpack2(q3.z, Cv + 12); unpack2(q3.w, Cv + 14);
}

__global__ __launch_bounds__(256) void scan_pass1(const float* __restrict__ A_log)
{
    int gid = blockIdx.x * 256 + threadIdx.x;
    int d = gid & (DI - 1);
    int c = (gid >> 9) & (NCHUNK - 1);
    int b = gid >> 15;

    float a[NSTATE];
    bool fast = true;
#pragma unroll
    for (int n = 0; n < NSTATE; n++) {
        a[n] = -__expf(A_log[d * NSTATE + n]);
        fast = fast && (fabsf(a[n] + (float)(n + 1)) < 1e-5f * (n + 1));
    }

    float h[NSTATE];
#pragma unroll
    for (int n = 0; n < NSTATE; n++) h[n] = 0.f;

    size_t base = (size_t)b * TOK_L + (size_t)c * CHUNK;
    size_t oidx = (((size_t)b * NCHUNK + c) * DI + d) * NSTATE;
    float P[NSTATE];

    if (fast) {
        float p = 1.f;
        for (int l = 0; l < CHUNK; l++) {
            size_t tt = base + l;
            float dtu = __bfloat162float(g_dtu[tt * DI + d]);
            float r   = g_rdt[tt * DI + d];
            p *= r;
            float w[NSTATE], Bv[NSTATE], Cv[NSTATE];
            pow_ladder(r, w);
            load_bc16(tt, Bv, Cv);
#pragma unroll
            for (int n = 0; n < NSTATE; n++)
                h[n] = fmaf(h[n], w[n], dtu * Bv[n]);
        }
        pow_ladder(p, P);
    } else {
        float dtsum = 0.f;
        for (int l = 0; l < CHUNK; l++) {
            size_t tt = base + l;
            float dtv = __bfloat162float(g_dt [tt * DI + d]);
            float dtu = __bfloat162float(g_dtu[tt * DI + d]);
            dtsum += dtv;
            float Bv[NSTATE], Cv[NSTATE];
            load_bc16(tt, Bv, Cv);
#pragma unroll
            for (int n = 0; n < NSTATE; n++)
                h[n] = fmaf(h[n], __expf(dtv * a[n]), dtu * Bv[n]);
        }
#pragma unroll
        for (int n = 0; n < NSTATE; n++) P[n] = __expf(a[n] * dtsum);
    }

    float4* ho = reinterpret_cast<float4*>(&g_hend[oidx]);
    float4* po = reinterpret_cast<float4*>(&g_Pend[oidx]);
#pragma unroll
    for (int q = 0; q < 4; q++) {
        ho[q] = make_float4(h[q * 4], h[q * 4 + 1], h[q * 4 + 2], h[q * 4 + 3]);
        po[q] = make_float4(P[q * 4], P[q * 4 + 1], P[q * 4 + 2], P[q * 4 + 3]);
    }
}

__global__ __launch_bounds__(256) void scan_pass2()
{
    int tid = blockIdx.x * 256 + threadIdx.x;
    int b  = tid >> 13;
    int dn = tid & 8191;
    float h = 0.f;
    for (int c = 0; c < NCHUNK; c++) {
        size_t idx = ((size_t)(b * NCHUNK + c)) * 8192 + dn;
        g_hstart[idx] = h;
        h = g_hend[idx] + g_Pend[idx] * h;
    }
}

__global__ __launch_bounds__(256) void scan_pass3(
    const float* __restrict__ A_log, const float* __restrict__ Dp)
{
    int gid = blockIdx.x * 256 + threadIdx.x;
    int d = gid & (DI - 1);
    int c = (gid >> 9) & (NCHUNK - 1);
    int b = gid >> 15;

    float a[NSTATE];
    bool fast = true;
#pragma unroll
    for (int n = 0; n < NSTATE; n++) {
        a[n] = -__expf(A_log[d * NSTATE + n]);
        fast = fast && (fabsf(a[n] + (float)(n + 1)) < 1e-5f * (n + 1));
    }
    float Dv = Dp[d];

    size_t sidx = (((size_t)b * NCHUNK + c) * DI + d) * NSTATE;
    float h[NSTATE];
    {
        const float4* hi = reinterpret_cast<const float4*>(&g_hstart[sidx]);
#pragma unroll
        for (int q = 0; q < 4; q++) {
            float4 v = hi[q];
            h[q * 4] = v.x; h[q * 4 + 1] = v.y; h[q * 4 + 2] = v.z; h[q * 4 + 3] = v.w;
        }
    }

    size_t base = (size_t)b * TOK_L + (size_t)c * CHUNK;
    for (int l = 0; l < CHUNK; l++) {
        size_t tt = base + l;
        float dtu = __bfloat162float(g_dtu[tt * DI + d]);
        float uv  = __bfloat162float(g_u  [tt * DI + d]);
        float zv  = __bfloat162float(g_z  [tt * DI + d]);
        float w[NSTATE], Bv[NSTATE], Cv[NSTATE];
        if (fast) {
            float r = g_rdt[tt * DI + d];
            pow_ladder(r, w);
        } else {
            float dtv = __bfloat162float(g_dt[tt * DI + d]);
#pragma unroll
            for (int n = 0; n < NSTATE; n++) w[n] = __expf(dtv * a[n]);
        }
        load_bc16(tt, Bv, Cv);
        float y0 = 0.f, y1 = 0.f, y2 = 0.f, y3 = 0.f;
#pragma unroll
        for (int n = 0; n < NSTATE; n += 4) {
            h[n]     = fmaf(h[n],     w[n],     dtu * Bv[n]);
            h[n + 1] = fmaf(h[n + 1], w[n + 1], dtu * Bv[n + 1]);
            h[n + 2] = fmaf(h[n + 2], w[n + 2], dtu * Bv[n + 2]);
            h[n + 3] = fmaf(h[n + 3], w[n + 3], dtu * Bv[n + 3]);
            y0 = fmaf(h[n],     Cv[n],     y0);
            y1 = fmaf(h[n + 1], Cv[n + 1], y1);
            y2 = fmaf(h[n + 2], Cv[n + 2], y2);
            y3 = fmaf(h[n + 3], Cv[n + 3], y3);
        }
        float y = (y0 + y1) + (y2 + y3);
        y = (y + uv * Dv) * (zv * sigmoidf_(zv));
        g_ybf[tt * DI + d] = __float2bfloat16(y);
    }
}

// ------------------------- LayerNorm + NCHW output -------------------------
__global__ __launch_bounds__(256) void ln_k(
    const float* __restrict__ g, const float* __restrict__ be,
    float* __restrict__ out)
{
    __shared__ float sm[32][257];
    int tid = threadIdx.x;
    int warp = tid >> 5, lane = tid & 31;
    int t0 = blockIdx.x * 32;

    for (int i = 0; i < 4; i++) {
        int tl = warp * 4 + i;
        int t  = t0 + tl;
        const float* row = g_res + (size_t)t * CDIM;
        float v[8];
        float s = 0.f, sq = 0.f;
#pragma unroll
        for (int r = 0; r < 2; r++) {
            float4 p = reinterpret_cast<const float4*>(row)[lane * 2 + r];
            v[r * 4] = p.x; v[r * 4 + 1] = p.y; v[r * 4 + 2] = p.z; v[r * 4 + 3] = p.w;
        }
#pragma unroll
        for (int k = 0; k < 8; k++) { s += v[k]; sq += v[k] * v[k]; }
#pragma unroll
        for (int o = 16; o; o >>= 1) {
            s  += __shfl_xor_sync(0xffffffffu, s,  o);
            sq += __shfl_xor_sync(0xffffffffu, sq, o);
        }
        float mu  = s * (1.f / CDIM);
        float var = sq * (1.f / CDIM) - mu * mu;
        float inv = rsqrtf(var + 1e-5f);
#pragma unroll
        for (int k = 0; k < 8; k++) {
            int c = lane * 8 + k;
            sm[tl][c] = (v[k] - mu) * inv * g[c] + be[c];
        }
    }
    __syncthreads();

    int bt = t0 >> 12;
    int l0 = t0 & (TOK_L - 1);
#pragma unroll 4
    for (int r = 0; r < 32; r++) {
        int idx = tid + 256 * r;
        int l = idx & 31;
        int c = idx >> 5;
        out[((size_t)bt * CDIM + c) * TOK_L + l0 + l] = sm[l][c];
    }
}

// ------------------------- launch ------------------------------------------
extern "C" void kernel_launch(void* const* d_in, const int* in_sizes, int n_in,
                              void* d_out, int out_size)
{
    const float* decoder  = (const float*)d_in[0];
    const float* encoder  = (const float*)d_in[1];
    const float* dec_w    = (const float*)d_in[2];
    const float* dec_b    = (const float*)d_in[3];
    const float* enc_w    = (const float*)d_in[4];
    const float* enc_b    = (const float*)d_in[5];
    const float* out_w    = (const float*)d_in[6];
    const float* out_b    = (const float*)d_in[7];
    const float* ln_g     = (const float*)d_in[8];
    const float* ln_b     = (const float*)d_in[9];
    const float* in_w     = (const float*)d_in[10];
    const float* in_b     = (const float*)d_in[11];
    const float* conv_w   = (const float*)d_in[12];
    const float* conv_b   = (const float*)d_in[13];
    const float* x_proj_w = (const float*)d_in[14];
    const float* dt_w     = (const float*)d_in[15];
    const float* dt_b     = (const float*)d_in[16];
    const float* A_log    = (const float*)d_in[17];
    const float* D_param  = (const float*)d_in[18];
    const float* m_out_w  = (const float*)d_in[19];
    const float* m_out_b  = (const float*)d_in[20];
    float* out = (float*)d_out;

    const int SMEM_GEMM = 3 * (64 * 128 + 64 * 256);   // 73728 bytes
    static int attr_done = 0;
    if (!attr_done) {
        cudaFuncSetAttribute(gemm_bf<EpiEnc  >, cudaFuncAttributeMaxDynamicSharedMemorySize, SMEM_GEMM);
        cudaFuncSetAttribute(gemm_bf<EpiDec  >, cudaFuncAttributeMaxDynamicSharedMemorySize, SMEM_GEMM);
        cudaFuncSetAttribute(gemm_bf<EpiXZ   >, cudaFuncAttributeMaxDynamicSharedMemorySize, SMEM_GEMM);
        cudaFuncSetAttribute(gemm_bf<EpiFused>, cudaFuncAttributeMaxDynamicSharedMemorySize, SMEM_GEMM);
        cudaFuncSetAttribute(gemm_bf<EpiMout >, cudaFuncAttributeMaxDynamicSharedMemorySize, SMEM_GEMM);
        cudaFuncSetAttribute(gemm_bf<EpiOut  >, cudaFuncAttributeMaxDynamicSharedMemorySize, SMEM_GEMM);
        attr_done = 1;
    }

    dim3 blk(256);
    const int MB = NTOK / 64;   // 128 M-tiles

    __nv_bfloat16 *wdec, *wenc, *win, *wmout, *wout, *wfused;
    __nv_bfloat16 *decbf, *encbf, *combbf, *ubf, *ybf, *gatedbf;
    cudaGetSymbolAddress((void**)&wdec,   g_wdec);
    cudaGetSymbolAddress((void**)&wenc,   g_wenc);
    cudaGetSymbolAddress((void**)&win,    g_win);
    cudaGetSymbolAddress((void**)&wmout,  g_wmout);
    cudaGetSymbolAddress((void**)&wout,   g_wout);
    cudaGetSymbolAddress((void**)&wfused, g_wfused);
    cudaGetSymbolAddress((void**)&decbf,  g_decbf);
    cudaGetSymbolAddress((void**)&encbf,  g_encbf);
    cudaGetSymbolAddress((void**)&combbf, g_combbf);
    cudaGetSymbolAddress((void**)&ubf,    g_u);
    cudaGetSymbolAddress((void**)&ybf,    g_ybf);
    cudaGetSymbolAddress((void**)&gatedbf,g_gatedbf);

    // weight prep + input transpose
    f2bf_all<<<(SZ_ALL + 255) / 256, blk>>>(dec_w, enc_w, in_w, m_out_w, out_w);
    wcomb_k<<<(DI * NFUSED + 255) / 256, blk>>>(x_proj_w, dt_w);
    nchw_to_bf2<<<2 * (NTOK / 32), blk>>>(decoder, encoder);

    // 1. enc_p = enc @ enc_w + enc_b               (K=256, N=512)
    gemm_bf<EpiEnc  ><<<dim3(DI / 128, MB), blk, SMEM_GEMM>>>(encbf, wenc, CDIM, DI, CDIM, EpiEnc{enc_b});
    // 2. dec_proj -> combined(bf16) + gate          (K=256, N=1024)
    gemm_bf<EpiDec  ><<<dim3(2 * DI / 128, MB), blk, SMEM_GEMM>>>(decbf, wdec, CDIM, 2 * DI, CDIM, EpiDec{dec_b});
    // 3. xz = combined @ in_w -> xm, z              (K=512, N=1024)
    gemm_bf<EpiXZ   ><<<dim3(2 * DI / 128, MB), blk, SMEM_GEMM>>>(combbf, win, DI, 2 * DI, DI, EpiXZ{in_b});
    // 4. depthwise conv + SiLU -> u (bf16, vectorized)
    conv_silu_k<<<NTOK * 64 / 256, blk>>>(conv_w, conv_b);
    // 5. fused: dt/r/dtu + B/C                      (K=512, N=640)
    gemm_bf<EpiFused><<<dim3(NFUSED / 128, MB), blk, SMEM_GEMM>>>(ubf, wfused, DI, NFUSED, DI, EpiFused{dt_b});
    // 6-8. chunked selective scan (16 states/thread)
    scan_pass1<<<NBATCH * NCHUNK * DI / 256, blk>>>(A_log);
    scan_pass2<<<NBATCH * DI * NSTATE / 256, blk>>>();
    scan_pass3<<<NBATCH * NCHUNK * DI / 256, blk>>>(A_log, D_param);
    // 9. processed = y @ m_out_w + b, * sigmoid(gate)  (K=512, N=512)
    gemm_bf<EpiMout ><<<dim3(DI / 128, MB), blk, SMEM_GEMM>>>(ybf, wmout, DI, DI, DI, EpiMout{m_out_b});
    // 10. out = gated @ out_w + out_b + dec        (K=512, N=256)
    gemm_bf<EpiOut  ><<<dim3(CDIM / 128, MB), blk, SMEM_GEMM>>>(gatedbf, wout, DI, CDIM, DI, EpiOut{out_b});
    // 11. LayerNorm + transpose to NCHW
    ln_k<<<NTOK / 32, blk>>>(ln_g, ln_b, out);
}

// round 14
// speedup vs baseline: 1.5030x; 1.1908x over previous
#include <cuda_runtime.h>
#include <cuda_bf16.h>
#include <math.h>
#include <stdint.h>

// Problem constants
#define TOK_L   4096
#define NBATCH  2
#define NTOK    8192
#define CDIM    256
#define DI      512
#define NSTATE  16
#define RRANK   32
#define CHUNK   64
#define NCHUNK  64
#define NFUSED  640          // 512 (dt) + 32 (B,C) + 96 pad

// ------------------------- scratch (device globals) -------------------------
__device__ float g_res   [NTOK * CDIM];
__device__ float g_decrow[NTOK * CDIM];
__device__ float g_rdt   [NTOK * DI];
__device__ float g_hend  [NBATCH * NCHUNK * DI * NSTATE];
__device__ float g_Pend  [NBATCH * NCHUNK * DI * NSTATE];
__device__ float g_hstart[NBATCH * NCHUNK * DI * NSTATE];

// bf16 activations
__device__ __nv_bfloat16 g_decbf  [NTOK * CDIM];
__device__ __nv_bfloat16 g_encbf  [NTOK * CDIM];
__device__ __nv_bfloat16 g_encp   [NTOK * DI];
__device__ __nv_bfloat16 g_gate   [NTOK * DI];
__device__ __nv_bfloat16 g_combbf [NTOK * DI];
__device__ __nv_bfloat16 g_xm     [NTOK * DI];
__device__ __nv_bfloat16 g_z      [NTOK * DI];
__device__ __nv_bfloat16 g_u      [NTOK * DI];
__device__ __nv_bfloat16 g_dt     [NTOK * DI];
__device__ __nv_bfloat16 g_dtu    [NTOK * DI];
__device__ __nv_bfloat16 g_bc     [NTOK * 32];
__device__ __nv_bfloat16 g_ybf    [NTOK * DI];
__device__ __nv_bfloat16 g_gatedbf[NTOK * DI];
// bf16 weights, row-major [K][N]
__device__ __nv_bfloat16 g_wdec  [CDIM * 2 * DI];
__device__ __nv_bfloat16 g_wenc  [CDIM * DI];
__device__ __nv_bfloat16 g_win   [DI * 2 * DI];
__device__ __nv_bfloat16 g_wmout [DI * DI];
__device__ __nv_bfloat16 g_wout  [DI * CDIM];
__device__ __nv_bfloat16 g_wfused[DI * NFUSED];

// ------------------------- helpers -----------------------------------------
__device__ __forceinline__ float sigmoidf_(float x) { return 1.f / (1.f + __expf(-x)); }

#define CP_ASYNC16(dst, src) \
    asm volatile("cp.async.cg.shared.global [%0], [%1], 16;\n" :: "r"(dst), "l"(src))
#define CP_COMMIT() asm volatile("cp.async.commit_group;\n" ::: "memory")
#define CP_WAIT1()  asm volatile("cp.async.wait_group 1;\n" ::: "memory")

#define LDSM_X4(r0,r1,r2,r3,addr) \
    asm volatile("ldmatrix.sync.aligned.m8n8.x4.shared.b16 {%0,%1,%2,%3}, [%4];" \
        : "=r"(r0),"=r"(r1),"=r"(r2),"=r"(r3) : "r"(addr))
#define LDSM_X4T(r0,r1,r2,r3,addr) \
    asm volatile("ldmatrix.sync.aligned.m8n8.x4.trans.shared.b16 {%0,%1,%2,%3}, [%4];" \
        : "=r"(r0),"=r"(r1),"=r"(r2),"=r"(r3) : "r"(addr))

#define MMA16816(d, a, b) \
    asm volatile("mma.sync.aligned.m16n8k16.row.col.f32.bf16.bf16.f32 " \
        "{%0,%1,%2,%3}, {%4,%5,%6,%7}, {%8,%9}, {%0,%1,%2,%3};" \
        : "+f"(d[0]),"+f"(d[1]),"+f"(d[2]),"+f"(d[3]) \
        : "r"(a[0]),"r"(a[1]),"r"(a[2]),"r"(a[3]), "r"(b[0]),"r"(b[1]))

// ------------------------- epilogue functors -------------------------------
struct EpiEnc {
    const float* b;
    __device__ void operator()(int t, int j, float a) const {
        g_encp[(size_t)t * DI + j] = __float2bfloat16(a + b[j]);
    }
};
struct EpiDec {
    const float* b;
    __device__ void operator()(int t, int j, float a) const {
        float v = a + b[j];
        if (j < DI) {
            float e = __bfloat162float(g_encp[(size_t)t * DI + j]);
            g_combbf[(size_t)t * DI + j] = __float2bfloat16(v * sigmoidf_(e) + e);
        } else {
            g_gate[(size_t)t * DI + (j - DI)] = __float2bfloat16(v);
        }
    }
};
struct EpiXZ {
    const float* b;
    __device__ void operator()(int t, int j, float a) const {
        float v = a + b[j];
        if (j < DI) g_xm[(size_t)t * DI + j] = __float2bfloat16(v);
        else        g_z [(size_t)t * DI + (j - DI)] = __float2bfloat16(v);
    }
};
struct EpiFused {
    const float* dtb;
    __device__ void operator()(int t, int j, float a) const {
        if (j < DI) {
            float x = a + dtb[j];
            float ex = __expf(x);
            float sp, r;
            if (x > 20.f) { sp = x; r = __expf(-x); }
            else          { sp = log1pf(ex); r = 1.f / (1.f + ex); }
            float uv = __bfloat162float(g_u[(size_t)t * DI + j]);
            g_dt [(size_t)t * DI + j] = __float2bfloat16(sp);
            g_dtu[(size_t)t * DI + j] = __float2bfloat16(sp * uv);
            g_rdt[(size_t)t * DI + j] = r;
        } else if (j < DI + 32) {
            g_bc[(size_t)t * 32 + (j - DI)] = __float2bfloat16(a);
        }
    }
};
struct EpiMout {
    const float* b;
    __device__ void operator()(int t, int j, float a) const {
        float v = a + b[j];
        float g = __bfloat162float(g_gate[(size_t)t * DI + j]);
        g_gatedbf[(size_t)t * DI + j] = __float2bfloat16(v * sigmoidf_(g));
    }
};
struct EpiOut {
    const float* b;
    __device__ void operator()(int t, int j, float a) const {
        g_res[(size_t)t * CDIM + j] = a + b[j] + g_decrow[(size_t)t * CDIM + j];
    }
};

// ------------------- bf16 tensor-core GEMM (BM=64, BN=128, occ 3) ----------
template <class Epi>
__global__ __launch_bounds__(256, 3) void gemm_bf(
    const __nv_bfloat16* __restrict__ A, const __nv_bfloat16* __restrict__ W,
    int K, int N, int lda, Epi epi)
{
    extern __shared__ char smem[];
    const int ASZ = 64 * 128;        // 64 rows x 64 bf16 (128B rows)
    const int BSZ = 64 * 256;        // 64 k-rows x 128 bf16 (256B rows)
    uint32_t sbase = (uint32_t)__cvta_generic_to_shared(smem);

    int tid = threadIdx.x;
    int w = tid >> 5, lane = tid & 31;
    int wm = w >> 2, wn = w & 3;     // 2 x 4 warps; warp tile 32x32
    int t0 = blockIdx.y * 64, n0 = blockIdx.x * 128;

    const __nv_bfloat16* Ab = A + (size_t)t0 * lda;
    const __nv_bfloat16* Wb = W + n0;

    auto loadStage = [&](int s, int k0) {
        uint32_t as = sbase + s * (ASZ + BSZ);
        uint32_t bs = as + ASZ;
#pragma unroll
        for (int r = 0; r < 2; r++) {
            int idx = tid + 256 * r;
            int m = idx >> 3, kb = idx & 7;
            uint32_t off = m * 128 + ((kb ^ (m & 7)) << 4);
            CP_ASYNC16(as + off, Ab + (size_t)m * lda + k0 + kb * 8);
        }
#pragma unroll
        for (int r = 0; r < 4; r++) {
            int idx = tid + 256 * r;
            int k = idx >> 4, nb = idx & 15;
            uint32_t off = k * 256 + ((nb >> 3) << 7) + (((nb & 7) ^ (k & 7)) << 4);
            CP_ASYNC16(bs + off, Wb + (size_t)(k0 + k) * N + nb * 8);
        }
    };

    float acc[2][4][4];
#pragma unroll
    for (int i = 0; i < 2; i++)
#pragma unroll
        for (int j = 0; j < 4; j++)
#pragma unroll
            for (int c = 0; c < 4; c++) acc[i][j][c] = 0.f;

    int nk = K / 64;
    loadStage(0, 0);
    CP_COMMIT();
    if (nk > 1) loadStage(1, 64);
    CP_COMMIT();

    for (int kt = 0; kt < nk; kt++) {
        CP_WAIT1();
        __syncthreads();
        int s = kt % 3;
        if (kt + 2 < nk) loadStage((kt + 2) % 3, (kt + 2) * 64);
        CP_COMMIT();

        uint32_t as = sbase + s * (ASZ + BSZ);
        uint32_t bs = as + ASZ;
        int sub = lane >> 3;
#pragma unroll
        for (int ks = 0; ks < 4; ks++) {
            uint32_t afr[2][4];
            uint32_t bfr[4][2];
#pragma unroll
            for (int i = 0; i < 2; i++) {
                int row = wm * 32 + i * 16 + (lane & 7) + ((sub & 1) << 3);
                int kb = ks * 2 + (sub >> 1);
                uint32_t addr = as + row * 128 + ((kb ^ (row & 7)) << 4);
                LDSM_X4(afr[i][0], afr[i][1], afr[i][2], afr[i][3], addr);
            }
#pragma unroll
            for (int p = 0; p < 2; p++) {
                int k = ks * 16 + (lane & 7) + ((sub & 1) << 3);
                int nb = wn * 4 + p * 2 + (sub >> 1);
                uint32_t addr = bs + k * 256 + ((nb >> 3) << 7) + (((nb & 7) ^ (k & 7)) << 4);
                uint32_t r0, r1, r2, r3;
                LDSM_X4T(r0, r1, r2, r3, addr);
                bfr[p * 2][0] = r0;     bfr[p * 2][1] = r1;
                bfr[p * 2 + 1][0] = r2; bfr[p * 2 + 1][1] = r3;
            }
#pragma unroll
            for (int i = 0; i < 2; i++)
#pragma unroll
                for (int j = 0; j < 4; j++) MMA16816(acc[i][j], afr[i], bfr[j]);
        }
    }

    int rbase = t0 + wm * 32 + (lane >> 2);
    int cbase = n0 + wn * 32 + (lane & 3) * 2;
#pragma unroll
    for (int i = 0; i < 2; i++)
#pragma unroll
        for (int j = 0; j < 4; j++) {
            epi(rbase + i * 16,     cbase + j * 8,     acc[i][j][0]);
            epi(rbase + i * 16,     cbase + j * 8 + 1, acc[i][j][1]);
            epi(rbase + i * 16 + 8, cbase + j * 8,     acc[i][j][2]);
            epi(rbase + i * 16 + 8, cbase + j * 8 + 1, acc[i][j][3]);
        }
}

// ------------------------- weight prep kernels ------------------------------
__global__ __launch_bounds__(256) void wcomb_k(
    const float* __restrict__ xproj, const float* __restrict__ dtw)
{
    int idx = blockIdx.x * 256 + threadIdx.x;
    if (idx >= DI * NFUSED) return;
    int k = idx / NFUSED, j = idx % NFUSED;
    float v = 0.f;
    if (j < DI) {
#pragma unroll
        for (int r = 0; r < RRANK; r++)
            v = fmaf(xproj[k * 64 + r], dtw[r * DI + j], v);
    } else if (j < DI + 32) {
        v = xproj[k * 64 + 32 + (j - DI)];
    }
    g_wfused[idx] = __float2bfloat16(v);
}

#define SZ_WDEC (CDIM * 2 * DI)
#define SZ_WENC (CDIM * DI)
#define SZ_WIN  (DI * 2 * DI)
#define SZ_WMOUT (DI * DI)
#define SZ_WOUT (DI * CDIM)
#define SZ_ALL  (SZ_WDEC + SZ_WENC + SZ_WIN + SZ_WMOUT + SZ_WOUT)

__global__ __launch_bounds__(256) void f2bf_all(
    const float* __restrict__ dec_w, const float* __restrict__ enc_w,
    const float* __restrict__ in_w, const float* __restrict__ m_out_w,
    const float* __restrict__ out_w)
{
    int i = blockIdx.x * 256 + threadIdx.x;
    if (i < SZ_WDEC) { g_wdec[i] = __float2bfloat16(dec_w[i]); return; }
    i -= SZ_WDEC;
    if (i < SZ_WENC) { g_wenc[i] = __float2bfloat16(enc_w[i]); return; }
    i -= SZ_WENC;
    if (i < SZ_WIN)  { g_win[i] = __float2bfloat16(in_w[i]); return; }
    i -= SZ_WIN;
    if (i < SZ_WMOUT){ g_wmout[i] = __float2bfloat16(m_out_w[i]); return; }
    i -= SZ_WMOUT;
    if (i < SZ_WOUT) { g_wout[i] = __float2bfloat16(out_w[i]); }
}

// ------------------------- NCHW -> row-major (bf16; dec also fp32) ---------
__global__ __launch_bounds__(256) void nchw_to_bf2(
    const float* __restrict__ dec, const float* __restrict__ enc)
{
    __shared__ float sm[32][257];
    int tid = threadIdx.x;
    int nblk = gridDim.x >> 1;
    int which = blockIdx.x >= nblk;
    const float* in = which ? enc : dec;
    __nv_bfloat16* out = which ? g_encbf : g_decbf;
    int t0 = (blockIdx.x - which * nblk) * 32;
    int bt = t0 >> 12, l0 = t0 & (TOK_L - 1);
    const float* src = in + (size_t)bt * CDIM * TOK_L + l0;
#pragma unroll 4
    for (int r = 0; r < 32; r++) {
        int idx = tid + 256 * r;
        int c = idx >> 5, l = idx & 31;
        sm[l][c] = src[(size_t)c * TOK_L + l];
    }
    __syncthreads();
#pragma unroll 4
    for (int r = 0; r < 32; r++) {
        int idx = tid + 256 * r;
        int c = idx & 255, l = idx >> 8;
        float v = sm[l][c];
        out[(size_t)(t0 + l) * CDIM + c] = __float2bfloat16(v);
        if (!which) g_decrow[(size_t)(t0 + l) * CDIM + c] = v;
    }
}

// ------------------------- depthwise causal conv (K=4) + SiLU --------------
__global__ __launch_bounds__(256) void conv_silu_k(
    const float* __restrict__ w, const float* __restrict__ bias)
{
    int t = blockIdx.x;
    int d = blockIdx.y * 256 + threadIdx.x;
    int l = t & (TOK_L - 1);
    float acc = bias[d];
#pragma unroll
    for (int k = 0; k < 4; k++) {
        int li = l - 3 + k;
        if (li >= 0)
            acc = fmaf(__bfloat162float(g_xm[(size_t)(t - 3 + k) * DI + d]), w[d * 4 + k], acc);
    }
    g_u[(size_t)t * DI + d] = __float2bfloat16(acc * sigmoidf_(acc));
}

// ------------------------- chunked selective scan (16 states / thread) ------
__device__ __forceinline__ void pow_ladder(float r, float* w) {
    w[0] = r;
    w[1] = r * r;
    w[2] = w[1] * r;    w[3] = w[1] * w[1];
    w[4] = w[3] * r;    w[5] = w[3] * w[1];  w[6] = w[3] * w[2];  w[7] = w[3] * w[3];
    w[8] = w[7] * r;    w[9] = w[7] * w[1];  w[10] = w[7] * w[2]; w[11] = w[7] * w[3];
    w[12] = w[7] * w[4];w[13] = w[7] * w[5]; w[14] = w[7] * w[6]; w[15] = w[7] * w[7];
}

__device__ __forceinline__ void load_bc16(size_t tt, float* Bv, float* Cv) {
    const uint4* p = reinterpret_cast<const uint4*>(&g_bc[tt * 32]);
    uint4 q0 = p[0], q1 = p[1], q2 = p[2], q3 = p[3];
    const uint32_t* bw = &q0.x;
#pragma unroll
    for (int i = 0; i < 8; i++) {
        __nv_bfloat162 v = *reinterpret_cast<const __nv_bfloat162*>(&bw[i]);
        float2 f = __bfloat1622float2(v);
        Bv[i * 2] = f.x; Bv[i * 2 + 1] = f.y;
    }
    const uint32_t* cw = &q2.x;
#pragma unroll
    for (int i = 0; i < 8; i++) {
        __nv_bfloat162 v = *reinterpret_cast<const __nv_bfloat162*>(&cw[i]);
        float2 f = __bfloat1622float2(v);
        Cv[i * 2] = f.x; Cv[i * 2 + 1] = f.y;
    }
}

__global__ __launch_bounds__(256) void scan_pass1(const float* __restrict__ A_log)
{
    int gid = blockIdx.x * 256 + threadIdx.x;
    int d = gid & (DI - 1);
    int c = (gid >> 9) & (NCHUNK - 1);
    int b = gid >> 15;

    float a[NSTATE];
    bool fast = true;
#pragma unroll
    for (int n = 0; n < NSTATE; n++) {
        a[n] = -__expf(A_log[d * NSTATE + n]);
        fast = fast && (fabsf(a[n] + (float)(n + 1)) < 1e-5f * (n + 1));
    }

    float h[NSTATE];
#pragma unroll
    for (int n = 0; n < NSTATE; n++) h[n] = 0.f;

    size_t base = (size_t)b * TOK_L + (size_t)c * CHUNK;
    size_t oidx = (((size_t)b * NCHUNK + c) * DI + d) * NSTATE;
    float P[NSTATE];

    if (fast) {
        float p = 1.f;
        for (int l = 0; l < CHUNK; l++) {
            size_t tt = base + l;
            float dtu = __bfloat162float(g_dtu[tt * DI + d]);
            float r   = g_rdt[tt * DI + d];
            p *= r;
            float w[NSTATE], Bv[NSTATE], Cv[NSTATE];
            pow_ladder(r, w);
            load_bc16(tt, Bv, Cv);
#pragma unroll
            for (int n = 0; n < NSTATE; n++)
                h[n] = fmaf(h[n], w[n], dtu * Bv[n]);
        }
        pow_ladder(p, P);
    } else {
        float dtsum = 0.f;
        for (int l = 0; l < CHUNK; l++) {
            size_t tt = base + l;
            float dtv = __bfloat162float(g_dt [tt * DI + d]);
            float dtu = __bfloat162float(g_dtu[tt * DI + d]);
            dtsum += dtv;
            float Bv[NSTATE], Cv[NSTATE];
            load_bc16(tt, Bv, Cv);
#pragma unroll
            for (int n = 0; n < NSTATE; n++)
                h[n] = fmaf(h[n], __expf(dtv * a[n]), dtu * Bv[n]);
        }
#pragma unroll
        for (int n = 0; n < NSTATE; n++) P[n] = __expf(a[n] * dtsum);
    }

    float4* ho = reinterpret_cast<float4*>(&g_hend[oidx]);
    float4* po = reinterpret_cast<float4*>(&g_Pend[oidx]);
#pragma unroll
    for (int q = 0; q < 4; q++) {
        ho[q] = make_float4(h[q * 4], h[q * 4 + 1], h[q * 4 + 2], h[q * 4 + 3]);
        po[q] = make_float4(P[q * 4], P[q * 4 + 1], P[q * 4 + 2], P[q * 4 + 3]);
    }
}

__global__ __launch_bounds__(256) void scan_pass2()
{
    int tid = blockIdx.x * 256 + threadIdx.x;
    int b  = tid >> 13;
    int dn = tid & 8191;
    float h = 0.f;
    for (int c = 0; c < NCHUNK; c++) {
        size_t idx = ((size_t)(b * NCHUNK + c)) * 8192 + dn;
        g_hstart[idx] = h;
        h = g_hend[idx] + g_Pend[idx] * h;
    }
}

__global__ __launch_bounds__(256) void scan_pass3(
    const float* __restrict__ A_log, const float* __restrict__ Dp)
{
    int gid = blockIdx.x * 256 + threadIdx.x;
    int d = gid & (DI - 1);
    int c = (gid >> 9) & (NCHUNK - 1);
    int b = gid >> 15;

    float a[NSTATE];
    bool fast = true;
#pragma unroll
    for (int n = 0; n < NSTATE; n++) {
        a[n] = -__expf(A_log[d * NSTATE + n]);
        fast = fast && (fabsf(a[n] + (float)(n + 1)) < 1e-5f * (n + 1));
    }
    float Dv = Dp[d];

    size_t sidx = (((size_t)b * NCHUNK + c) * DI + d) * NSTATE;
    float h[NSTATE];
    {
        const float4* hi = reinterpret_cast<const float4*>(&g_hstart[sidx]);
#pragma unroll
        for (int q = 0; q < 4; q++) {
            float4 v = hi[q];
            h[q * 4] = v.x; h[q * 4 + 1] = v.y; h[q * 4 + 2] = v.z; h[q * 4 + 3] = v.w;
        }
    }

    size_t base = (size_t)b * TOK_L + (size_t)c * CHUNK;
    for (int l = 0; l < CHUNK; l++) {
        size_t tt = base + l;
        float dtu = __bfloat162float(g_dtu[tt * DI + d]);
        float uv  = __bfloat162float(g_u  [tt * DI + d]);
        float zv  = __bfloat162float(g_z  [tt * DI + d]);
        float w[NSTATE], Bv[NSTATE], Cv[NSTATE];
        if (fast) {
            float r = g_rdt[tt * DI + d];
            pow_ladder(r, w);
        } else {
            float dtv = __bfloat162float(g_dt[tt * DI + d]);
#pragma unroll
            for (int n = 0; n < NSTATE; n++) w[n] = __expf(dtv * a[n]);
        }
        load_bc16(tt, Bv, Cv);
        float y0 = 0.f, y1 = 0.f, y2 = 0.f, y3 = 0.f;
#pragma unroll
        for (int n = 0; n < NSTATE; n += 4) {
            h[n]     = fmaf(h[n],     w[n],     dtu * Bv[n]);
            h[n + 1] = fmaf(h[n + 1], w[n + 1], dtu * Bv[n + 1]);
            h[n + 2] = fmaf(h[n + 2], w[n + 2], dtu * Bv[n + 2]);
            h[n + 3] = fmaf(h[n + 3], w[n + 3], dtu * Bv[n + 3]);
            y0 = fmaf(h[n],     Cv[n],     y0);
            y1 = fmaf(h[n + 1], Cv[n + 1], y1);
            y2 = fmaf(h[n + 2], Cv[n + 2], y2);
            y3 = fmaf(h[n + 3], Cv[n + 3], y3);
        }
        float y = (y0 + y1) + (y2 + y3);
        y = (y + uv * Dv) * (zv * sigmoidf_(zv));
        g_ybf[tt * DI + d] = __float2bfloat16(y);
    }
}

// ------------------------- LayerNorm + NCHW output -------------------------
__global__ __launch_bounds__(256) void ln_k(
    const float* __restrict__ g, const float* __restrict__ be,
    float* __restrict__ out)
{
    __shared__ float sm[32][257];
    int tid = threadIdx.x;
    int warp = tid >> 5, lane = tid & 31;
    int t0 = blockIdx.x * 32;

    for (int i = 0; i < 4; i++) {
        int tl = warp * 4 + i;
        int t  = t0 + tl;
        const float* row = g_res + (size_t)t * CDIM;
        float v[8];
        float s = 0.f, sq = 0.f;
#pragma unroll
        for (int r = 0; r < 2; r++) {
            float4 p = reinterpret_cast<const float4*>(row)[lane * 2 + r];
            v[r * 4] = p.x; v[r * 4 + 1] = p.y; v[r * 4 + 2] = p.z; v[r * 4 + 3] = p.w;
        }
#pragma unroll
        for (int k = 0; k < 8; k++) { s += v[k]; sq += v[k] * v[k]; }
#pragma unroll
        for (int o = 16; o; o >>= 1) {
            s  += __shfl_xor_sync(0xffffffffu, s,  o);
            sq += __shfl_xor_sync(0xffffffffu, sq, o);
        }
        float mu  = s * (1.f / CDIM);
        float var = sq * (1.f / CDIM) - mu * mu;
        float inv = rsqrtf(var + 1e-5f);
#pragma unroll
        for (int k = 0; k < 8; k++) {
            int c = lane * 8 + k;
            sm[tl][c] = (v[k] - mu) * inv * g[c] + be[c];
        }
    }
    __syncthreads();

    int bt = t0 >> 12;
    int l0 = t0 & (TOK_L - 1);
#pragma unroll 4
    for (int r = 0; r < 32; r++) {
        int idx = tid + 256 * r;
        int l = idx & 31;
        int c = idx >> 5;
        out[((size_t)bt * CDIM + c) * TOK_L + l0 + l] = sm[l][c];
    }
}

// ------------------------- launch ------------------------------------------
extern "C" void kernel_launch(void* const* d_in, const int* in_sizes, int n_in,
                              void* d_out, int out_size)
{
    const float* decoder  = (const float*)d_in[0];
    const float* encoder  = (const float*)d_in[1];
    const float* dec_w    = (const float*)d_in[2];
    const float* dec_b    = (const float*)d_in[3];
    const float* enc_w    = (const float*)d_in[4];
    const float* enc_b    = (const float*)d_in[5];
    const float* out_w    = (const float*)d_in[6];
    const float* out_b    = (const float*)d_in[7];
    const float* ln_g     = (const float*)d_in[8];
    const float* ln_b     = (const float*)d_in[9];
    const float* in_w     = (const float*)d_in[10];
    const float* in_b     = (const float*)d_in[11];
    const float* conv_w   = (const float*)d_in[12];
    const float* conv_b   = (const float*)d_in[13];
    const float* x_proj_w = (const float*)d_in[14];
    const float* dt_w     = (const float*)d_in[15];
    const float* dt_b     = (const float*)d_in[16];
    const float* A_log    = (const float*)d_in[17];
    const float* D_param  = (const float*)d_in[18];
    const float* m_out_w  = (const float*)d_in[19];
    const float* m_out_b  = (const float*)d_in[20];
    float* out = (float*)d_out;

    const int SMEM_GEMM = 3 * (64 * 128 + 64 * 256);   // 73728 bytes
    static int attr_done = 0;
    if (!attr_done) {
        cudaFuncSetAttribute(gemm_bf<EpiEnc  >, cudaFuncAttributeMaxDynamicSharedMemorySize, SMEM_GEMM);
        cudaFuncSetAttribute(gemm_bf<EpiDec  >, cudaFuncAttributeMaxDynamicSharedMemorySize, SMEM_GEMM);
        cudaFuncSetAttribute(gemm_bf<EpiXZ   >, cudaFuncAttributeMaxDynamicSharedMemorySize, SMEM_GEMM);
        cudaFuncSetAttribute(gemm_bf<EpiFused>, cudaFuncAttributeMaxDynamicSharedMemorySize, SMEM_GEMM);
        cudaFuncSetAttribute(gemm_bf<EpiMout >, cudaFuncAttributeMaxDynamicSharedMemorySize, SMEM_GEMM);
        cudaFuncSetAttribute(gemm_bf<EpiOut  >, cudaFuncAttributeMaxDynamicSharedMemorySize, SMEM_GEMM);
        attr_done = 1;
    }

    dim3 blk(256);
    const int MB = NTOK / 64;   // 128 M-tiles

    __nv_bfloat16 *wdec, *wenc, *win, *wmout, *wout, *wfused;
    __nv_bfloat16 *decbf, *encbf, *combbf, *ubf, *ybf, *gatedbf;
    cudaGetSymbolAddress((void**)&wdec,   g_wdec);
    cudaGetSymbolAddress((void**)&wenc,   g_wenc);
    cudaGetSymbolAddress((void**)&win,    g_win);
    cudaGetSymbolAddress((void**)&wmout,  g_wmout);
    cudaGetSymbolAddress((void**)&wout,   g_wout);
    cudaGetSymbolAddress((void**)&wfused, g_wfused);
    cudaGetSymbolAddress((void**)&decbf,  g_decbf);
    cudaGetSymbolAddress((void**)&encbf,  g_encbf);
    cudaGetSymbolAddress((void**)&combbf, g_combbf);
    cudaGetSymbolAddress((void**)&ubf,    g_u);
    cudaGetSymbolAddress((void**)&ybf,    g_ybf);
    cudaGetSymbolAddress((void**)&gatedbf,g_gatedbf);

    // weight prep + input transpose
    f2bf_all<<<(SZ_ALL + 255) / 256, blk>>>(dec_w, enc_w, in_w, m_out_w, out_w);
    wcomb_k<<<(DI * NFUSED + 255) / 256, blk>>>(x_proj_w, dt_w);
    nchw_to_bf2<<<2 * (NTOK / 32), blk>>>(decoder, encoder);

    // 1. enc_p = enc @ enc_w + enc_b               (K=256, N=512)
    gemm_bf<EpiEnc  ><<<dim3(DI / 128, MB), blk, SMEM_GEMM>>>(encbf, wenc, CDIM, DI, CDIM, EpiEnc{enc_b});
    // 2. dec_proj -> combined(bf16) + gate          (K=256, N=1024)
    gemm_bf<EpiDec  ><<<dim3(2 * DI / 128, MB), blk, SMEM_GEMM>>>(decbf, wdec, CDIM, 2 * DI, CDIM, EpiDec{dec_b});
    // 3. xz = combined @ in_w -> xm, z              (K=512, N=1024)
    gemm_bf<EpiXZ   ><<<dim3(2 * DI / 128, MB), blk, SMEM_GEMM>>>(combbf, win, DI, 2 * DI, DI, EpiXZ{in_b});
    // 4. depthwise conv + SiLU -> u (bf16)
    conv_silu_k<<<dim3(NTOK, DI / 256), blk>>>(conv_w, conv_b);
    // 5. fused: dt/r/dtu + B/C                      (K=512, N=640)
    gemm_bf<EpiFused><<<dim3(NFUSED / 128, MB), blk, SMEM_GEMM>>>(ubf, wfused, DI, NFUSED, DI, EpiFused{dt_b});
    // 6-8. chunked selective scan (16 states/thread)
    scan_pass1<<<NBATCH * NCHUNK * DI / 256, blk>>>(A_log);
    scan_pass2<<<NBATCH * DI * NSTATE / 256, blk>>>();
    scan_pass3<<<NBATCH * NCHUNK * DI / 256, blk>>>(A_log, D_param);
    // 9. processed = y @ m_out_w + b, * sigmoid(gate)  (K=512, N=512)
    gemm_bf<EpiMout ><<<dim3(DI / 128, MB), blk, SMEM_GEMM>>>(ybf, wmout, DI, DI, DI, EpiMout{m_out_b});
    // 10. out = gated @ out_w + out_b + dec        (K=512, N=256)
    gemm_bf<EpiOut  ><<<dim3(CDIM / 128, MB), blk, SMEM_GEMM>>>(gatedbf, wout, DI, CDIM, DI, EpiOut{out_b});
    // 11. LayerNorm + transpose to NCHW
    ln_k<<<NTOK / 32, blk>>>(ln_g, ln_b, out);
}